// round 1
// baseline (speedup 1.0000x reference)
#include <cuda_runtime.h>
#include <math.h>

#define HIDDEN   4096
#define NEXP     128
#define TOPK     8
#define MAXT     16384

#define TM 128
#define TN 128
#define TK 8

// Scratch for logits [T, 128] (8 MB) — static device array, no allocation.
__device__ float g_logits[(size_t)MAXT * NEXP];

// ---------------------------------------------------------------------------
// Kernel 1: logits = X @ W^T   (X:[T,4096] fp32, W:[128,4096] fp32)
// Classic smem-tiled SGEMM, 128x128 tile, 8x8 micro-tile, 256 threads.
// ---------------------------------------------------------------------------
__global__ __launch_bounds__(256) void router_gemm_kernel(
    const float* __restrict__ X, const float* __restrict__ W, int T)
{
    __shared__ float xs[TK][TM + 4];   // k-major, padded
    __shared__ float ws[TK][TN + 4];

    const int tid = threadIdx.x;
    const int tx  = tid & 15;          // n sub-block 0..15
    const int ty  = tid >> 4;          // m sub-block 0..15
    const int m0  = blockIdx.x * TM;

    const int lr = tid >> 1;           // load row 0..127
    const int lc = (tid & 1) * 4;      // load k offset 0 or 4

    float acc[8][8];
#pragma unroll
    for (int i = 0; i < 8; i++)
#pragma unroll
        for (int j = 0; j < 8; j++) acc[i][j] = 0.f;

    const float* xptr = X + (size_t)(m0 + lr) * HIDDEN + lc;
    const float* wptr = W + (size_t)lr * HIDDEN + lc;

    for (int k0 = 0; k0 < HIDDEN; k0 += TK) {
        float4 xa = *(const float4*)(xptr + k0);
        float4 wa = *(const float4*)(wptr + k0);
        __syncthreads();
        xs[lc + 0][lr] = xa.x; xs[lc + 1][lr] = xa.y;
        xs[lc + 2][lr] = xa.z; xs[lc + 3][lr] = xa.w;
        ws[lc + 0][lr] = wa.x; ws[lc + 1][lr] = wa.y;
        ws[lc + 2][lr] = wa.z; ws[lc + 3][lr] = wa.w;
        __syncthreads();

#pragma unroll
        for (int kk = 0; kk < TK; kk++) {
            float a[8], b[8];
            *(float4*)&a[0] = *(const float4*)&xs[kk][ty * 8];
            *(float4*)&a[4] = *(const float4*)&xs[kk][ty * 8 + 4];
            *(float4*)&b[0] = *(const float4*)&ws[kk][tx * 8];
            *(float4*)&b[4] = *(const float4*)&ws[kk][tx * 8 + 4];
#pragma unroll
            for (int i = 0; i < 8; i++)
#pragma unroll
                for (int j = 0; j < 8; j++)
                    acc[i][j] = fmaf(a[i], b[j], acc[i][j]);
        }
    }

    // Epilogue: write logits.
#pragma unroll
    for (int i = 0; i < 8; i++) {
        size_t row = (size_t)(m0 + ty * 8 + i) * NEXP + tx * 8;
        *(float4*)&g_logits[row + 0] = *(const float4*)&acc[i][0];
        *(float4*)&g_logits[row + 4] = *(const float4*)&acc[i][4];
    }
}

// ---------------------------------------------------------------------------
// Kernel 2: sigmoid -> top-8 (selection score = sigmoid + bias, jax tie-break
// = lowest index) -> normalize -> write [indices_as_float | weights].
// One warp per token.
// ---------------------------------------------------------------------------
__global__ __launch_bounds__(256) void router_topk_kernel(
    const float* __restrict__ bias, float* __restrict__ out, int T)
{
    const int warp = (int)((blockIdx.x * (size_t)blockDim.x + threadIdx.x) >> 5);
    const int lane = threadIdx.x & 31;
    if (warp >= T) return;

    const float* Lr = g_logits + (size_t)warp * NEXP;

    float sv[4];   // selection scores
    float wv[4];   // weights (raw sigmoid)
#pragma unroll
    for (int i = 0; i < 4; i++) {
        int e = i * 32 + lane;
        float logit = Lr[e];
        float sc = 1.f / (1.f + expf(-logit));
        wv[i] = sc;
        sv[i] = sc + bias[e];
    }

    float wsel[TOPK];
    int   isel[TOPK];
    float wsum = 0.f;

#pragma unroll
    for (int k = 0; k < TOPK; k++) {
        // local argmax over this lane's 4 experts
        float bs = -INFINITY; int bi = 0x7fffffff; float bw = 0.f;
#pragma unroll
        for (int i = 0; i < 4; i++) {
            int e = i * 32 + lane;
            if (sv[i] > bs || (sv[i] == bs && e < bi)) {
                bs = sv[i]; bi = e; bw = wv[i];
            }
        }
        // warp butterfly argmax carrying (score, index, weight)
#pragma unroll
        for (int off = 16; off; off >>= 1) {
            float os = __shfl_xor_sync(0xffffffffu, bs, off);
            int   oi = __shfl_xor_sync(0xffffffffu, bi, off);
            float ow = __shfl_xor_sync(0xffffffffu, bw, off);
            if (os > bs || (os == bs && oi < bi)) { bs = os; bi = oi; bw = ow; }
        }
        isel[k] = bi;
        wsel[k] = bw;
        wsum += bw;
        // mask the winner (all lanes agree on bi)
#pragma unroll
        for (int i = 0; i < 4; i++)
            if (i * 32 + lane == bi) sv[i] = -INFINITY;
    }

    if (lane == 0) {
        float inv = 1.f / (wsum + 1e-20f);   // ROUTED_SCALING = 1.0
#pragma unroll
        for (int k = 0; k < TOPK; k++) {
            out[(size_t)warp * TOPK + k]                      = (float)isel[k];
            out[(size_t)T * TOPK + (size_t)warp * TOPK + k]   = wsel[k] * inv;
        }
    }
}

// ---------------------------------------------------------------------------
extern "C" void kernel_launch(void* const* d_in, const int* in_sizes, int n_in,
                              void* d_out, int out_size)
{
    const float* X    = (const float*)d_in[0];   // hidden_states [T, 4096]
    const float* W    = (const float*)d_in[1];   // weight [128, 4096]
    const float* bias = (const float*)d_in[2];   // e_score_correction_bias [128]
    float* out = (float*)d_out;

    const int T = in_sizes[0] / HIDDEN;          // 16384

    router_gemm_kernel<<<T / TM, 256>>>(X, W, T);
    router_topk_kernel<<<(T * 32 + 255) / 256, 256>>>(bias, out, T);
}